// round 15
// baseline (speedup 1.0000x reference)
#include <cuda_runtime.h>
#include <math.h>

// ---------------------------------------------------------------------------
// EfficientDet (BiFPN W=88, 3 stages, D=4 head) on GB300, fp32 direct convs.
// R14: pw_kernel -> 4 consecutive px/thread (float4 in+out);
//      fused sepconv for small levels (h<=16) only; heads unchanged (R13).
// ---------------------------------------------------------------------------

#define BATCH 4
#define WC 88
#define ATOT 49104

namespace cfg {
constexpr int HS[5]      = {64, 32, 16, 8, 4};
constexpr int HW_[5]     = {4096, 1024, 256, 64, 16};
constexpr int CIN_LAT[5] = {40, 80, 112, 192, 320};

constexpr long long REG_BASE  = (long long)BATCH * ATOT * 90;            // 17,677,440
constexpr long long ANCH_BASE = REG_BASE + (long long)BATCH * ATOT * 4;  // 18,463,104

constexpr int LVL_N[5]   = {BATCH*WC*4096, BATCH*WC*1024, BATCH*WC*256, BATCH*WC*64, BATCH*WC*16};
constexpr int LVL_OFF[5] = {0, 1441792, 1802240, 1892352, 1914880};
constexpr int PYR_N = 1920512;
constexpr int TOFF[5] = {0, 0, 360448, 450560, 0};   // td buffers (P4t,P5t,P6t)
constexpr int T_N = 473088;

constexpr int OFF_P   = 0;
constexpr int OFF_O   = OFF_P + PYR_N;
constexpr int OFF_T   = OFF_O + PYR_N;
constexpr int OFF_DW  = OFF_T + T_N;
constexpr int OFF_HR1 = OFF_DW + LVL_N[0];
constexpr int OFF_HR2 = OFF_HR1 + PYR_N;
constexpr int OFF_HC1 = OFF_HR2 + PYR_N;
constexpr int OFF_HC2 = OFF_HC1 + PYR_N;
constexpr int OFF_WT  = OFF_HC2 + PYR_N;

constexpr int WT_LAT[5] = {0, 3520, 10560, 20416, 37312};
constexpr int WT_BIFPW  = 65472;
constexpr int TWN       = WC * 9 * WC;                  // 69,696
constexpr int WT_REGTW  = WT_BIFPW + 24 * WC * WC;
constexpr int WT_CLSTW  = WT_REGTW + 4 * TWN;
constexpr int WT_REGOW  = WT_CLSTW + 4 * TWN;
constexpr int WT_CLSOW  = WT_REGOW + WC * 9 * 36;
constexpr int WT_TOTAL  = WT_CLSOW + WC * 9 * 812;
constexpr int SCRATCH_N = OFF_WT + WT_TOTAL;
}

// Zero-initialized scratch (padding lanes of transposed cls weights stay 0).
__device__ __align__(16) float g_scratch[cfg::SCRATCH_N];

// Level tables for the fused head-conv launches.
__constant__ int c_lvloff[5] = {0, 1441792, 1802240, 1892352, 1914880};
__constant__ int c_aoff[5]   = {0, 36864, 46080, 48384, 48960};

// ---------------------------------------------------------------------------
// cp.async helpers
// ---------------------------------------------------------------------------
__device__ __forceinline__ unsigned int smem_u32(const void* p) {
    return (unsigned int)__cvta_generic_to_shared(p);
}
__device__ __forceinline__ void cp_async4(unsigned int dst, const void* src, bool ok) {
    int sz = ok ? 4 : 0;
    asm volatile("cp.async.ca.shared.global [%0], [%1], 4, %2;"
                 :: "r"(dst), "l"(src), "r"(sz));
}
__device__ __forceinline__ void cp_commit() {
    asm volatile("cp.async.commit_group;");
}
template <int N>
__device__ __forceinline__ void cp_wait() {
    asm volatile("cp.async.wait_group %0;" :: "n"(N));
}

// ---------------------------------------------------------------------------
// Weight transpose: w[co][ci][k] -> wt[(ci*K+k)*CoutP + co]  (batched via z)
// ---------------------------------------------------------------------------
__global__ void transpose_w_kernel(const float* __restrict__ w, float* __restrict__ wt,
                                   int Cout, int Cin, int K, int CoutP) {
    int bidx = blockIdx.z;
    w  += (size_t)bidx * Cout * Cin * K;
    wt += (size_t)bidx * Cin * K * CoutP;
    int i = blockIdx.x * blockDim.x + threadIdx.x;
    int total = Cout * Cin * K;
    if (i >= total) return;
    int k  = i % K;
    int ci = (i / K) % Cin;
    int co = i / (K * Cin);
    wt[(ci * K + k) * CoutP + co] = w[i];
}

// ---------------------------------------------------------------------------
// Pointwise 1x1 conv (+bias, optional ReLU). Cout mult of 4 (=88).
// block 256 = 64 pixel-lanes x 4 co-lanes; each thread: 4 CONSECUTIVE pixels
// (one LDG.128 per ci) x 4 co. HW is always a multiple of 4.
// grid: (ceil(HW/256), ceil(Cout/16), B)
// ---------------------------------------------------------------------------
template <bool RELU>
__global__ void __launch_bounds__(256) pw_kernel(
        const float* __restrict__ in, const float* __restrict__ wt,
        const float* __restrict__ bias, float* __restrict__ out,
        int Cin, int Cout, int HW) {
    int tid  = threadIdx.x;
    int lane = tid >> 6;
    int p0   = blockIdx.x * 256 + (tid & 63) * 4;
    int co0  = blockIdx.y * 16 + lane * 4;
    int b    = blockIdx.z;
    if (co0 >= Cout || p0 >= HW) return;

    float a[4][4];   // [pixel][co]
#pragma unroll
    for (int j = 0; j < 4; j++) {
        a[j][0] = bias[co0 + 0]; a[j][1] = bias[co0 + 1];
        a[j][2] = bias[co0 + 2]; a[j][3] = bias[co0 + 3];
    }

    const float* inb = in + (size_t)b * Cin * HW;
    const float4* wt4 = (const float4*)wt;
    int cs4 = Cout >> 2;
    int w0i = co0 >> 2;
    for (int ci = 0; ci < Cin; ci++) {
        float4 w = wt4[ci * cs4 + w0i];
        float4 v = *(const float4*)(inb + (size_t)ci * HW + p0);
        a[0][0] += w.x * v.x; a[0][1] += w.y * v.x; a[0][2] += w.z * v.x; a[0][3] += w.w * v.x;
        a[1][0] += w.x * v.y; a[1][1] += w.y * v.y; a[1][2] += w.z * v.y; a[1][3] += w.w * v.y;
        a[2][0] += w.x * v.z; a[2][1] += w.y * v.z; a[2][2] += w.z * v.z; a[2][3] += w.w * v.z;
        a[3][0] += w.x * v.w; a[3][1] += w.y * v.w; a[3][2] += w.z * v.w; a[3][3] += w.w * v.w;
    }

    size_t ob0 = ((size_t)(b * Cout + co0)) * HW + p0;
#pragma unroll
    for (int k = 0; k < 4; k++) {
        float4 r;
        r.x = a[0][k]; r.y = a[1][k]; r.z = a[2][k]; r.w = a[3][k];
        if (RELU) {
            r.x = fmaxf(r.x, 0.f); r.y = fmaxf(r.y, 0.f);
            r.z = fmaxf(r.z, 0.f); r.w = fmaxf(r.w, 0.f);
        }
        *(float4*)(out + ob0 + (size_t)k * HW) = r;
    }
}

// ---------------------------------------------------------------------------
// Depthwise 3x3 with fused normalized-fusion input, computed on the fly.
// MODE 0: fuse2 + up2(Bh)    MODE 1: fuse3 + down2(Cf)    MODE 2: fuse2 + down2(Cf)
// ---------------------------------------------------------------------------
template <int MODE>
__global__ void dw_fuse_kernel(const float* __restrict__ A, const float* __restrict__ Bh,
                               const float* __restrict__ Tm, const float* __restrict__ Cf,
                               const float* __restrict__ dww, const float* __restrict__ fw,
                               float* __restrict__ out, int h) {
    int idx = blockIdx.x * blockDim.x + threadIdx.x;
    int total = BATCH * WC * h * h;
    if (idx >= total) return;
    int x = idx % h;
    int y = (idx / h) % h;
    int c = (idx / (h * h)) % WC;
    int b = idx / (WC * h * h);

    float w0, w1, w2 = 0.f;
    if (MODE == 1) {
        w0 = fmaxf(fw[0], 0.f); w1 = fmaxf(fw[1], 0.f); w2 = fmaxf(fw[2], 0.f);
        float s = w0 + w1 + w2 + 1e-4f; w0 /= s; w1 /= s; w2 /= s;
    } else {
        w0 = fmaxf(fw[0], 0.f); w1 = fmaxf(fw[1], 0.f);
        float s = w0 + w1 + 1e-4f; w0 /= s; w1 /= s;
    }

    int h2 = h >> 1, hf = h << 1;
    size_t chan = (size_t)(b * WC + c);
    const float* Ab = A + chan * h * h;
    const float* Bb = (MODE == 0) ? Bh + chan * h2 * h2 : nullptr;
    const float* Tb = (MODE == 1) ? Tm + chan * h * h : nullptr;
    const float* Cb = (MODE != 0) ? Cf + chan * hf * hf : nullptr;
    const float* wd = dww + c * 9;

    float acc = 0.f;
#pragma unroll
    for (int ky = 0; ky < 3; ky++) {
        int yy = y + ky - 1;
        if ((unsigned)yy >= (unsigned)h) continue;
#pragma unroll
        for (int kx = 0; kx < 3; kx++) {
            int xx = x + kx - 1;
            if ((unsigned)xx >= (unsigned)h) continue;
            float v = w0 * Ab[yy * h + xx];
            if (MODE == 0) {
                v += w1 * Bb[(yy >> 1) * h2 + (xx >> 1)];
            } else {
                float m = fmaxf(fmaxf(Cb[(2*yy)*hf + 2*xx],     Cb[(2*yy)*hf + 2*xx + 1]),
                                fmaxf(Cb[(2*yy+1)*hf + 2*xx],   Cb[(2*yy+1)*hf + 2*xx + 1]));
                if (MODE == 1) v += w1 * Tb[yy * h + xx] + w2 * m;
                else           v += w1 * m;
            }
            acc += wd[ky * 3 + kx] * v;
        }
    }
    out[idx] = acc;
}

// ---------------------------------------------------------------------------
// Fully fused sepconv for SMALL levels (h<=16): fuse + dw3x3 + pw1x1 + ReLU.
// block 256; tile = 8x8 px, all 88 channels staged through smem.
// ---------------------------------------------------------------------------
template <int MODE>
__global__ void __launch_bounds__(256) sepconv_kernel(
        const float* __restrict__ A, const float* __restrict__ Bh,
        const float* __restrict__ Tm, const float* __restrict__ Cf,
        const float* __restrict__ dww, const float* __restrict__ fw,
        const float* __restrict__ pwt, const float* __restrict__ pbias,
        float* __restrict__ out, int h) {
    __shared__ float s_dw[WC * 64];

    int b = blockIdx.z;
    int tilesRow = (h + 7) >> 3;
    int ty0 = (blockIdx.x / tilesRow) * 8;
    int tx0 = (blockIdx.x % tilesRow) * 8;
    int tid = threadIdx.x;

    float w0, w1, w2 = 0.f;
    if (MODE == 1) {
        w0 = fmaxf(fw[0], 0.f); w1 = fmaxf(fw[1], 0.f); w2 = fmaxf(fw[2], 0.f);
        float s = w0 + w1 + w2 + 1e-4f; w0 /= s; w1 /= s; w2 /= s;
    } else {
        w0 = fmaxf(fw[0], 0.f); w1 = fmaxf(fw[1], 0.f);
        float s = w0 + w1 + 1e-4f; w0 /= s; w1 /= s;
    }

    int h2 = h >> 1, hf = h << 1;

    // ---- Phase A: depthwise into smem ----
#pragma unroll 2
    for (int i = tid; i < WC * 64; i += 256) {
        int ci = i >> 6, p = i & 63;
        int y = ty0 + (p >> 3), x = tx0 + (p & 7);
        float acc = 0.f;
        if (y < h && x < h) {
            size_t chan = (size_t)(b * WC + ci);
            const float* Ab = A + chan * h * h;
            const float* Bb = (MODE == 0) ? Bh + chan * h2 * h2 : nullptr;
            const float* Tb = (MODE == 1) ? Tm + chan * h * h : nullptr;
            const float* Cb = (MODE != 0) ? Cf + chan * hf * hf : nullptr;
            const float* wd = dww + ci * 9;
#pragma unroll
            for (int ky = 0; ky < 3; ky++) {
                int yy = y + ky - 1;
                if ((unsigned)yy >= (unsigned)h) continue;
#pragma unroll
                for (int kx = 0; kx < 3; kx++) {
                    int xx = x + kx - 1;
                    if ((unsigned)xx >= (unsigned)h) continue;
                    float v = w0 * Ab[yy * h + xx];
                    if (MODE == 0) {
                        v += w1 * Bb[(yy >> 1) * h2 + (xx >> 1)];
                    } else {
                        float m = fmaxf(fmaxf(Cb[(2*yy)*hf + 2*xx],   Cb[(2*yy)*hf + 2*xx + 1]),
                                        fmaxf(Cb[(2*yy+1)*hf + 2*xx], Cb[(2*yy+1)*hf + 2*xx + 1]));
                        if (MODE == 1) v += w1 * Tb[yy * h + xx] + w2 * m;
                        else           v += w1 * m;
                    }
                    acc += wd[ky * 3 + kx] * v;
                }
            }
        }
        s_dw[i] = acc;
    }
    __syncthreads();

    // ---- Phase B: pointwise from smem ----
    int px = tid & 63, lane = tid >> 6;
    int y = ty0 + (px >> 3), x = tx0 + (px & 7);
    if (y >= h || x >= h) return;

    const float4* w4 = (const float4*)pwt;
    const float* sp = s_dw + px;
    size_t st = (size_t)h * h;
    for (int q = lane; q < WC / 4; q += 4) {
        int co0 = q * 4;
        float a0 = pbias[co0], a1 = pbias[co0 + 1], a2 = pbias[co0 + 2], a3 = pbias[co0 + 3];
#pragma unroll 8
        for (int ci = 0; ci < WC; ci++) {
            float v  = sp[ci * 64];
            float4 w = w4[ci * (WC / 4) + q];
            a0 += w.x * v; a1 += w.y * v; a2 += w.z * v; a3 += w.w * v;
        }
        size_t ob = ((size_t)(b * WC + co0) * h + y) * h + x;
        out[ob]          = fmaxf(a0, 0.f);
        out[ob + st]     = fmaxf(a1, 0.f);
        out[ob + 2 * st] = fmaxf(a2, 0.f);
        out[ob + 3 * st] = fmaxf(a3, 0.f);
    }
}

// ---------------------------------------------------------------------------
// conv3x3 core (heads): Cin=88 in 8 chunks of 11, cp.async double-buffered.
// Tile 16x16, thread = 1x4 px x 4 co, smem rows padded to 20 floats.
// ---------------------------------------------------------------------------
#define CICH 11
#define SROW 20
#define SCH  (CICH * 18 * SROW)   // 3960 floats per buffer

struct LevelTile { int l, h, ty0, tx0; };

__device__ __forceinline__ LevelTile decode_tile(int bx) {
    LevelTile lt;
    int t;
    if (bx < 16)      { lt.l = 0; t = bx; }
    else if (bx < 20) { lt.l = 1; t = bx - 16; }
    else              { lt.l = bx - 18; t = 0; }
    lt.h = 64 >> lt.l;
    int tilesRow = (lt.l == 0) ? 4 : (lt.l == 1) ? 2 : 1;
    lt.ty0 = (t / tilesRow) * 16;
    lt.tx0 = (t % tilesRow) * 16;
    return lt;
}

__device__ __forceinline__ void stage_chunk(const float* __restrict__ inb, int cc,
                                            int h, int ty0, int tx0,
                                            float* sb, int tid) {
#pragma unroll 2
    for (int i = tid; i < CICH * 324; i += 256) {
        int ci = i / 324, r = i - ci * 324;
        int py = r / 18, px = r - py * 18;
        int gy = ty0 + py - 1, gx = tx0 + px - 1;
        bool ok = ((unsigned)gy < (unsigned)h) && ((unsigned)gx < (unsigned)h);
        const float* g = inb + ((size_t)(cc + ci) * h + (ok ? gy : 0)) * h + (ok ? gx : 0);
        cp_async4(smem_u32(sb + ci * (18 * SROW) + py * SROW + px), g, ok);
    }
}

__device__ __forceinline__ void conv3x3_core(
        const float* __restrict__ inb, const float4* __restrict__ wt4,
        int rs4, int c4, bool active,
        int h, int ty0, int tx0,
        float* s_in, int tid, int qy, int qx,
        float acc[4][4]) {
    const float* sp0 = s_in + qy * SROW + 4 * qx;
    stage_chunk(inb, 0, h, ty0, tx0, s_in, tid);
    cp_commit();

    const int NCH = WC / CICH;   // 8
    for (int k = 0; k < NCH; k++) {
        if (k + 1 < NCH) {
            stage_chunk(inb, (k + 1) * CICH, h, ty0, tx0, s_in + ((k + 1) & 1) * SCH, tid);
            cp_commit();
            cp_wait<1>();
        } else {
            cp_wait<0>();
        }
        __syncthreads();

        if (active) {
            const float* spk = sp0 + (k & 1) * SCH;
            for (int ci = 0; ci < CICH; ci++) {
                const float* s = spk + ci * (18 * SROW);
                float v[3][6];
#pragma unroll
                for (int r = 0; r < 3; r++) {
                    float4 u0 = *(const float4*)(s + r * SROW);
                    float2 u1 = *(const float2*)(s + r * SROW + 4);
                    v[r][0] = u0.x; v[r][1] = u0.y; v[r][2] = u0.z; v[r][3] = u0.w;
                    v[r][4] = u1.x; v[r][5] = u1.y;
                }
                int cig = k * CICH + ci;
                const float4* wp = wt4 + (size_t)cig * 9 * rs4 + c4;
#pragma unroll
                for (int ky = 0; ky < 3; ky++) {
#pragma unroll
                    for (int kx = 0; kx < 3; kx++) {
                        float4 w = wp[(ky * 3 + kx) * rs4];
#pragma unroll
                        for (int px2 = 0; px2 < 4; px2++) {
                            float vv = v[ky][px2 + kx];
                            acc[px2][0] += w.x * vv;
                            acc[px2][1] += w.y * vv;
                            acc[px2][2] += w.z * vv;
                            acc[px2][3] += w.w * vv;
                        }
                    }
                }
            }
        }
        __syncthreads();
    }
}

// ---------------------------------------------------------------------------
// Fused reg+cls tower conv layer: grid (23, 12, B). 64 regs, 4 blocks/SM.
// ---------------------------------------------------------------------------
__global__ void __launch_bounds__(256, 4) conv3x3_tower(
        const float* __restrict__ inR, const float* __restrict__ inC,
        const float* __restrict__ wtR, const float* __restrict__ wtC,
        const float* __restrict__ bR,  const float* __restrict__ bC,
        float* __restrict__ outR, float* __restrict__ outC) {
    __shared__ float s_in[2 * SCH];

    LevelTile lt = decode_tile(blockIdx.x);
    int b   = blockIdx.z;
    int tid = threadIdx.x;
    int lane = tid >> 6;
    int p    = tid & 63;
    int qx = p & 3, qy = p >> 2;

    int side  = blockIdx.y >= 6;
    int chunk = blockIdx.y - side * 6;
    const float* in  = side ? inC : inR;
    const float* wt  = side ? wtC : wtR;
    const float* bb  = side ? bC  : bR;
    float* out       = side ? outC : outR;

    int co0 = chunk * 16 + lane * 4;
    bool active = (co0 < WC);

    float acc[4][4];
    {
        float b0 = active ? bb[co0 + 0] : 0.f;
        float b1 = active ? bb[co0 + 1] : 0.f;
        float b2 = active ? bb[co0 + 2] : 0.f;
        float b3 = active ? bb[co0 + 3] : 0.f;
#pragma unroll
        for (int j = 0; j < 4; j++) { acc[j][0] = b0; acc[j][1] = b1; acc[j][2] = b2; acc[j][3] = b3; }
    }

    const float* inb = in + c_lvloff[lt.l] + (size_t)b * WC * lt.h * lt.h;
    conv3x3_core(inb, (const float4*)wt, WC >> 2, co0 >> 2, active,
                 lt.h, lt.ty0, lt.tx0, s_in, tid, qy, qx, acc);

    if (!active) return;
    int oy = lt.ty0 + qy, ox = lt.tx0 + 4 * qx;
    if (oy >= lt.h || ox >= lt.h) return;

    float* ob = out + c_lvloff[lt.l] + ((size_t)(b * WC + co0) * lt.h + oy) * lt.h + ox;
    size_t st = (size_t)lt.h * lt.h;
#pragma unroll
    for (int i = 0; i < 4; i++) {
        float4 r;
        r.x = fmaxf(acc[0][i], 0.f); r.y = fmaxf(acc[1][i], 0.f);
        r.z = fmaxf(acc[2][i], 0.f); r.w = fmaxf(acc[3][i], 0.f);
        *(float4*)(ob + i * st) = r;
    }
}

// ---------------------------------------------------------------------------
// Fused output convs: grid (23, 54, B).
// ---------------------------------------------------------------------------
__global__ void __launch_bounds__(256, 4) conv3x3_out(
        const float* __restrict__ inR, const float* __restrict__ inC,
        const float* __restrict__ wtR, const float* __restrict__ wtC,
        const float* __restrict__ bR,  const float* __restrict__ bC,
        float* __restrict__ outR, float* __restrict__ outC) {
    __shared__ float s_in[2 * SCH];

    LevelTile lt = decode_tile(blockIdx.x);
    int b   = blockIdx.z;
    int tid = threadIdx.x;
    int lane = tid >> 6;
    int p    = tid & 63;
    int qx = p & 3, qy = p >> 2;

    bool isReg = (blockIdx.y < 3);
    int chunk  = isReg ? blockIdx.y : blockIdx.y - 3;
    int Cout   = isReg ? 36 : 810;
    int CoutP  = isReg ? 36 : 812;
    int outCh  = isReg ? 4 : 90;
    const float* in = isReg ? inR : inC;
    const float* wt = isReg ? wtR : wtC;
    const float* bb = isReg ? bR  : bC;
    float* out      = isReg ? outR : outC;

    int co0 = chunk * 16 + lane * 4;
    bool active = (co0 < Cout);

    float acc[4][4];
    {
        float b0 = (co0 + 0 < Cout) ? bb[co0 + 0] : 0.f;
        float b1 = (co0 + 1 < Cout) ? bb[co0 + 1] : 0.f;
        float b2 = (co0 + 2 < Cout) ? bb[co0 + 2] : 0.f;
        float b3 = (co0 + 3 < Cout) ? bb[co0 + 3] : 0.f;
#pragma unroll
        for (int j = 0; j < 4; j++) { acc[j][0] = b0; acc[j][1] = b1; acc[j][2] = b2; acc[j][3] = b3; }
    }

    const float* inb = in + c_lvloff[lt.l] + (size_t)b * WC * lt.h * lt.h;
    conv3x3_core(inb, (const float4*)wt, CoutP >> 2, co0 >> 2, active,
                 lt.h, lt.ty0, lt.tx0, s_in, tid, qy, qx, acc);

    if (!active) return;
    int oy = lt.ty0 + qy, ox = lt.tx0 + 4 * qx;
    if (oy >= lt.h || ox >= lt.h) return;

#pragma unroll
    for (int px2 = 0; px2 < 4; px2++) {
        int gai = c_aoff[lt.l] + (oy * lt.h + ox + px2) * 9;
#pragma unroll
        for (int i = 0; i < 4; i++) {
            int co = co0 + i;
            if (co >= Cout) break;
            int ai = co / outCh;
            int oc = co - ai * outCh;
            float vv = acc[px2][i];
            if (!isReg) vv = 1.f / (1.f + __expf(-vv));
            out[((size_t)b * ATOT + gai + ai) * outCh + oc] = vv;
        }
    }
}

// ---------------------------------------------------------------------------
// Anchors (RetinaNet-style, img_size=512, levels 3..7)
// ---------------------------------------------------------------------------
__global__ void anchors_kernel(float* __restrict__ out) {
    int i = blockIdx.x * blockDim.x + threadIdx.x;
    if (i >= ATOT) return;
    const int offs[6] = {0, 36864, 46080, 48384, 48960, 49104};
    int l = 0;
    while (i >= offs[l + 1]) l++;
    int fs = 64 >> l;
    float stride = (float)(8 << l);
    float size   = (float)(32 << l);
    int r = i - offs[l];
    int a = r % 9;
    int p = r / 9;
    int px = p % fs, py = p / fs;
    float cx = (px + 0.5f) * stride;
    float cy = (py + 0.5f) * stride;
    int ri = a / 3, si = a % 3;
    const float ratios[3] = {0.5f, 1.0f, 2.0f};
    float scale = exp2f((float)si * (1.0f / 3.0f));
    float sr = sqrtf(ratios[ri]);
    float w = size * scale / sr;
    float hh = size * scale * sr;
    out[i * 4 + 0] = cx - 0.5f * w;
    out[i * 4 + 1] = cy - 0.5f * hh;
    out[i * 4 + 2] = cx + 0.5f * w;
    out[i * 4 + 3] = cy + 0.5f * hh;
}

// ---------------------------------------------------------------------------
// Host orchestration
// ---------------------------------------------------------------------------
extern "C" void kernel_launch(void* const* d_in, const int* in_sizes, int n_in,
                              void* d_out, int out_size) {
    (void)in_sizes; (void)n_in; (void)out_size;
    using namespace cfg;

    const float* cIn[5]; const float* latw[5]; const float* latb[5];
    for (int l = 0; l < 5; l++) {
        cIn[l]  = (const float*)d_in[3 * l + 0];
        latw[l] = (const float*)d_in[3 * l + 1];
        latb[l] = (const float*)d_in[3 * l + 2];
    }
    const float* bif_dw  = (const float*)d_in[15];
    const float* bif_pw  = (const float*)d_in[16];
    const float* bif_pb  = (const float*)d_in[17];
    const float* bif_fw2 = (const float*)d_in[18];
    const float* bif_fw3 = (const float*)d_in[19];
    const float* reg_tw  = (const float*)d_in[20];
    const float* reg_tb  = (const float*)d_in[21];
    const float* reg_ow  = (const float*)d_in[22];
    const float* reg_ob  = (const float*)d_in[23];
    const float* cls_tw  = (const float*)d_in[24];
    const float* cls_tb  = (const float*)d_in[25];
    const float* cls_ow  = (const float*)d_in[26];
    const float* cls_ob  = (const float*)d_in[27];
    float* outp = (float*)d_out;

    float* S = nullptr;
    cudaGetSymbolAddress((void**)&S, g_scratch);
    float* P   = S + OFF_P;
    float* O   = S + OFF_O;
    float* T   = S + OFF_T;
    float* DW  = S + OFF_DW;
    float* HR1 = S + OFF_HR1;
    float* HR2 = S + OFF_HR2;
    float* HC1 = S + OFF_HC1;
    float* HC2 = S + OFF_HC2;
    float* WT  = S + OFF_WT;

    // ---- weight transposes ----
    for (int l = 0; l < 5; l++) {
        int tot = WC * CIN_LAT[l];
        transpose_w_kernel<<<(tot + 255) / 256, 256>>>(latw[l], WT + WT_LAT[l], WC, CIN_LAT[l], 1, WC);
    }
    transpose_w_kernel<<<dim3((WC*WC + 255) / 256, 1, 24), 256>>>(bif_pw, WT + WT_BIFPW, WC, WC, 1, WC);
    transpose_w_kernel<<<dim3((TWN + 255) / 256, 1, 4), 256>>>(reg_tw, WT + WT_REGTW, WC, WC, 9, WC);
    transpose_w_kernel<<<dim3((TWN + 255) / 256, 1, 4), 256>>>(cls_tw, WT + WT_CLSTW, WC, WC, 9, WC);
    transpose_w_kernel<<<(36*WC*9 + 255) / 256, 256>>>(reg_ow, WT + WT_REGOW, 36, WC, 9, 36);
    transpose_w_kernel<<<(810*WC*9 + 255) / 256, 256>>>(cls_ow, WT + WT_CLSOW, 810, WC, 9, 812);

    // ---- lateral 1x1 convs (no relu) ----
    for (int l = 0; l < 5; l++) {
        dim3 g((HW_[l] + 255) / 256, (WC + 15) / 16, BATCH);
        pw_kernel<false><<<g, 256>>>(cIn[l], WT + WT_LAT[l], latb[l], P + LVL_OFF[l],
                                     CIN_LAT[l], WC, HW_[l]);
    }

    // ---- BiFPN stages: split dw+pw for P3/P4 (l<2), fused sepconv for l>=2 ----
    float* cur = P;
    float* nxt = O;
    for (int s = 0; s < 3; s++) {
        const float* dwW = bif_dw + (size_t)s * 8 * WC * 9;
        const float* pwT = WT + WT_BIFPW + (size_t)s * 8 * WC * WC;
        const float* pbb = bif_pb + (size_t)s * 8 * WC;
        const float* f2  = bif_fw2 + s * 10;
        const float* f3  = bif_fw3 + s * 9;

        auto pw = [&](int j, int h, float* dst) {
            dim3 g((h * h + 255) / 256, (WC + 15) / 16, BATCH);
            pw_kernel<true><<<g, 256>>>(DW, pwT + j * WC * WC, pbb + j * WC, dst, WC, WC, h * h);
        };
        auto fgrid = [&](int h) {
            int tr = (h + 7) >> 3;
            return dim3(tr * tr, 1, BATCH);
        };
        auto sep_up = [&](int l, const float* A, const float* Bh, int j, const float* fwp, float* dst) {
            int h = HS[l];
            if (l >= 2) {
                sepconv_kernel<0><<<fgrid(h), 256>>>(A, Bh, nullptr, nullptr,
                    dwW + j * WC * 9, fwp, pwT + j * WC * WC, pbb + j * WC, dst, h);
            } else {
                int n = BATCH * WC * h * h;
                dw_fuse_kernel<0><<<(n + 255) / 256, 256>>>(A, Bh, nullptr, nullptr,
                    dwW + j * WC * 9, fwp, DW, h);
                pw(j, h, dst);
            }
        };
        auto sep3 = [&](int l, const float* A, const float* Tm, const float* Cf, int j, const float* fwp, float* dst) {
            int h = HS[l];
            if (l >= 2) {
                sepconv_kernel<1><<<fgrid(h), 256>>>(A, nullptr, Tm, Cf,
                    dwW + j * WC * 9, fwp, pwT + j * WC * WC, pbb + j * WC, dst, h);
            } else {
                int n = BATCH * WC * h * h;
                dw_fuse_kernel<1><<<(n + 255) / 256, 256>>>(A, nullptr, Tm, Cf,
                    dwW + j * WC * 9, fwp, DW, h);
                pw(j, h, dst);
            }
        };
        auto sep_dn = [&](int l, const float* A, const float* Cf, int j, const float* fwp, float* dst) {
            int h = HS[l];
            if (l >= 2) {
                sepconv_kernel<2><<<fgrid(h), 256>>>(A, nullptr, nullptr, Cf,
                    dwW + j * WC * 9, fwp, pwT + j * WC * WC, pbb + j * WC, dst, h);
            } else {
                int n = BATCH * WC * h * h;
                dw_fuse_kernel<2><<<(n + 255) / 256, 256>>>(A, nullptr, nullptr, Cf,
                    dwW + j * WC * 9, fwp, DW, h);
                pw(j, h, dst);
            }
        };

        // top-down
        sep_up(3, cur + LVL_OFF[3], cur + LVL_OFF[4], 0, f2 + 0, T + TOFF[3]);   // p6t
        sep_up(2, cur + LVL_OFF[2], T + TOFF[3],      1, f2 + 2, T + TOFF[2]);   // p5t
        sep_up(1, cur + LVL_OFF[1], T + TOFF[2],      2, f2 + 4, T + TOFF[1]);   // p4t
        sep_up(0, cur + LVL_OFF[0], T + TOFF[1],      3, f2 + 6, nxt + LVL_OFF[0]); // p3o
        // bottom-up
        sep3(1, cur + LVL_OFF[1], T + TOFF[1], nxt + LVL_OFF[0], 4, f3 + 0, nxt + LVL_OFF[1]); // p4o
        sep3(2, cur + LVL_OFF[2], T + TOFF[2], nxt + LVL_OFF[1], 5, f3 + 3, nxt + LVL_OFF[2]); // p5o
        sep3(3, cur + LVL_OFF[3], T + TOFF[3], nxt + LVL_OFF[2], 6, f3 + 6, nxt + LVL_OFF[3]); // p6o
        sep_dn(4, cur + LVL_OFF[4], nxt + LVL_OFF[3], 7, f2 + 8, nxt + LVL_OFF[4]);            // p7o

        float* tmp = cur; cur = nxt; nxt = tmp;
    }
    // final pyramid is in `cur`

    // ---- heads: 4 fused tower layers + 1 fused output layer ----
    dim3 gT(23, 12, BATCH);
    dim3 gO(23, 54, BATCH);

    conv3x3_tower<<<gT, 256>>>(cur, cur,
                               WT + WT_REGTW + 0 * TWN, WT + WT_CLSTW + 0 * TWN,
                               reg_tb + 0,   cls_tb + 0,   HR1, HC1);
    conv3x3_tower<<<gT, 256>>>(HR1, HC1,
                               WT + WT_REGTW + 1 * TWN, WT + WT_CLSTW + 1 * TWN,
                               reg_tb + 88,  cls_tb + 88,  HR2, HC2);
    conv3x3_tower<<<gT, 256>>>(HR2, HC2,
                               WT + WT_REGTW + 2 * TWN, WT + WT_CLSTW + 2 * TWN,
                               reg_tb + 176, cls_tb + 176, HR1, HC1);
    conv3x3_tower<<<gT, 256>>>(HR1, HC1,
                               WT + WT_REGTW + 3 * TWN, WT + WT_CLSTW + 3 * TWN,
                               reg_tb + 264, cls_tb + 264, HR2, HC2);
    conv3x3_out<<<gO, 256>>>(HR2, HC2,
                             WT + WT_REGOW, WT + WT_CLSOW,
                             reg_ob, cls_ob,
                             outp + REG_BASE, outp);

    // ---- anchors ----
    anchors_kernel<<<(ATOT + 255) / 256, 256>>>(outp + ANCH_BASE);
}

// round 16
// speedup vs baseline: 1.1165x; 1.1165x over previous
#include <cuda_runtime.h>
#include <math.h>

// ---------------------------------------------------------------------------
// EfficientDet (BiFPN W=88, 3 stages, D=4 head) on GB300, fp32 direct convs.
// R16: exact R13 structure (split dw+pw BiFPN, occupancy-4 heads) + pw_kernel
//      with 4 consecutive pixels/thread (LDG.128 input reads).
// ---------------------------------------------------------------------------

#define BATCH 4
#define WC 88
#define ATOT 49104

namespace cfg {
constexpr int HS[5]      = {64, 32, 16, 8, 4};
constexpr int HW_[5]     = {4096, 1024, 256, 64, 16};
constexpr int CIN_LAT[5] = {40, 80, 112, 192, 320};

constexpr long long REG_BASE  = (long long)BATCH * ATOT * 90;            // 17,677,440
constexpr long long ANCH_BASE = REG_BASE + (long long)BATCH * ATOT * 4;  // 18,463,104

constexpr int LVL_N[5]   = {BATCH*WC*4096, BATCH*WC*1024, BATCH*WC*256, BATCH*WC*64, BATCH*WC*16};
constexpr int LVL_OFF[5] = {0, 1441792, 1802240, 1892352, 1914880};
constexpr int PYR_N = 1920512;
constexpr int TOFF[5] = {0, 0, 360448, 450560, 0};   // td buffers (P4t,P5t,P6t)
constexpr int T_N = 473088;

constexpr int OFF_P   = 0;
constexpr int OFF_O   = OFF_P + PYR_N;
constexpr int OFF_T   = OFF_O + PYR_N;
constexpr int OFF_DW  = OFF_T + T_N;
constexpr int OFF_HR1 = OFF_DW + LVL_N[0];
constexpr int OFF_HR2 = OFF_HR1 + PYR_N;
constexpr int OFF_HC1 = OFF_HR2 + PYR_N;
constexpr int OFF_HC2 = OFF_HC1 + PYR_N;
constexpr int OFF_WT  = OFF_HC2 + PYR_N;

constexpr int WT_LAT[5] = {0, 3520, 10560, 20416, 37312};
constexpr int WT_BIFPW  = 65472;
constexpr int TWN       = WC * 9 * WC;                  // 69,696
constexpr int WT_REGTW  = WT_BIFPW + 24 * WC * WC;
constexpr int WT_CLSTW  = WT_REGTW + 4 * TWN;
constexpr int WT_REGOW  = WT_CLSTW + 4 * TWN;
constexpr int WT_CLSOW  = WT_REGOW + WC * 9 * 36;
constexpr int WT_TOTAL  = WT_CLSOW + WC * 9 * 812;
constexpr int SCRATCH_N = OFF_WT + WT_TOTAL;
}

// Zero-initialized scratch (padding lanes of transposed cls weights stay 0).
__device__ __align__(16) float g_scratch[cfg::SCRATCH_N];

// Level tables for the fused head-conv launches.
__constant__ int c_lvloff[5] = {0, 1441792, 1802240, 1892352, 1914880};
__constant__ int c_aoff[5]   = {0, 36864, 46080, 48384, 48960};

// ---------------------------------------------------------------------------
// cp.async helpers
// ---------------------------------------------------------------------------
__device__ __forceinline__ unsigned int smem_u32(const void* p) {
    return (unsigned int)__cvta_generic_to_shared(p);
}
__device__ __forceinline__ void cp_async4(unsigned int dst, const void* src, bool ok) {
    int sz = ok ? 4 : 0;
    asm volatile("cp.async.ca.shared.global [%0], [%1], 4, %2;"
                 :: "r"(dst), "l"(src), "r"(sz));
}
__device__ __forceinline__ void cp_commit() {
    asm volatile("cp.async.commit_group;");
}
template <int N>
__device__ __forceinline__ void cp_wait() {
    asm volatile("cp.async.wait_group %0;" :: "n"(N));
}

// ---------------------------------------------------------------------------
// Weight transpose: w[co][ci][k] -> wt[(ci*K+k)*CoutP + co]  (batched via z)
// ---------------------------------------------------------------------------
__global__ void transpose_w_kernel(const float* __restrict__ w, float* __restrict__ wt,
                                   int Cout, int Cin, int K, int CoutP) {
    int bidx = blockIdx.z;
    w  += (size_t)bidx * Cout * Cin * K;
    wt += (size_t)bidx * Cin * K * CoutP;
    int i = blockIdx.x * blockDim.x + threadIdx.x;
    int total = Cout * Cin * K;
    if (i >= total) return;
    int k  = i % K;
    int ci = (i / K) % Cin;
    int co = i / (K * Cin);
    wt[(ci * K + k) * CoutP + co] = w[i];
}

// ---------------------------------------------------------------------------
// Pointwise 1x1 conv (+bias, optional ReLU). Cout mult of 4 (=88).
// block 256 = 64 pixel-lanes x 4 co-lanes; each thread: 4 CONSECUTIVE pixels
// (one LDG.128 per ci) x 4 co. HW is always a multiple of 4.
// grid: (ceil(HW/256), ceil(Cout/16), B)
// ---------------------------------------------------------------------------
template <bool RELU>
__global__ void __launch_bounds__(256) pw_kernel(
        const float* __restrict__ in, const float* __restrict__ wt,
        const float* __restrict__ bias, float* __restrict__ out,
        int Cin, int Cout, int HW) {
    int tid  = threadIdx.x;
    int lane = tid >> 6;
    int p0   = blockIdx.x * 256 + (tid & 63) * 4;
    int co0  = blockIdx.y * 16 + lane * 4;
    int b    = blockIdx.z;
    if (co0 >= Cout || p0 >= HW) return;

    float a[4][4];   // [pixel][co]
#pragma unroll
    for (int j = 0; j < 4; j++) {
        a[j][0] = bias[co0 + 0]; a[j][1] = bias[co0 + 1];
        a[j][2] = bias[co0 + 2]; a[j][3] = bias[co0 + 3];
    }

    const float* inb = in + (size_t)b * Cin * HW;
    const float4* wt4 = (const float4*)wt;
    int cs4 = Cout >> 2;
    int w0i = co0 >> 2;
    for (int ci = 0; ci < Cin; ci++) {
        float4 w = wt4[ci * cs4 + w0i];
        float4 v = *(const float4*)(inb + (size_t)ci * HW + p0);
        a[0][0] += w.x * v.x; a[0][1] += w.y * v.x; a[0][2] += w.z * v.x; a[0][3] += w.w * v.x;
        a[1][0] += w.x * v.y; a[1][1] += w.y * v.y; a[1][2] += w.z * v.y; a[1][3] += w.w * v.y;
        a[2][0] += w.x * v.z; a[2][1] += w.y * v.z; a[2][2] += w.z * v.z; a[2][3] += w.w * v.z;
        a[3][0] += w.x * v.w; a[3][1] += w.y * v.w; a[3][2] += w.z * v.w; a[3][3] += w.w * v.w;
    }

    size_t ob0 = ((size_t)(b * Cout + co0)) * HW + p0;
#pragma unroll
    for (int k = 0; k < 4; k++) {
        float4 r;
        r.x = a[0][k]; r.y = a[1][k]; r.z = a[2][k]; r.w = a[3][k];
        if (RELU) {
            r.x = fmaxf(r.x, 0.f); r.y = fmaxf(r.y, 0.f);
            r.z = fmaxf(r.z, 0.f); r.w = fmaxf(r.w, 0.f);
        }
        *(float4*)(out + ob0 + (size_t)k * HW) = r;
    }
}

// ---------------------------------------------------------------------------
// Depthwise 3x3 with fused normalized-fusion input, computed on the fly.
// MODE 0: fuse2 + up2(Bh)    MODE 1: fuse3 + down2(Cf)    MODE 2: fuse2 + down2(Cf)
// ---------------------------------------------------------------------------
template <int MODE>
__global__ void dw_fuse_kernel(const float* __restrict__ A, const float* __restrict__ Bh,
                               const float* __restrict__ Tm, const float* __restrict__ Cf,
                               const float* __restrict__ dww, const float* __restrict__ fw,
                               float* __restrict__ out, int h) {
    int idx = blockIdx.x * blockDim.x + threadIdx.x;
    int total = BATCH * WC * h * h;
    if (idx >= total) return;
    int x = idx % h;
    int y = (idx / h) % h;
    int c = (idx / (h * h)) % WC;
    int b = idx / (WC * h * h);

    float w0, w1, w2 = 0.f;
    if (MODE == 1) {
        w0 = fmaxf(fw[0], 0.f); w1 = fmaxf(fw[1], 0.f); w2 = fmaxf(fw[2], 0.f);
        float s = w0 + w1 + w2 + 1e-4f; w0 /= s; w1 /= s; w2 /= s;
    } else {
        w0 = fmaxf(fw[0], 0.f); w1 = fmaxf(fw[1], 0.f);
        float s = w0 + w1 + 1e-4f; w0 /= s; w1 /= s;
    }

    int h2 = h >> 1, hf = h << 1;
    size_t chan = (size_t)(b * WC + c);
    const float* Ab = A + chan * h * h;
    const float* Bb = (MODE == 0) ? Bh + chan * h2 * h2 : nullptr;
    const float* Tb = (MODE == 1) ? Tm + chan * h * h : nullptr;
    const float* Cb = (MODE != 0) ? Cf + chan * hf * hf : nullptr;
    const float* wd = dww + c * 9;

    float acc = 0.f;
#pragma unroll
    for (int ky = 0; ky < 3; ky++) {
        int yy = y + ky - 1;
        if ((unsigned)yy >= (unsigned)h) continue;
#pragma unroll
        for (int kx = 0; kx < 3; kx++) {
            int xx = x + kx - 1;
            if ((unsigned)xx >= (unsigned)h) continue;
            float v = w0 * Ab[yy * h + xx];
            if (MODE == 0) {
                v += w1 * Bb[(yy >> 1) * h2 + (xx >> 1)];
            } else {
                float m = fmaxf(fmaxf(Cb[(2*yy)*hf + 2*xx],     Cb[(2*yy)*hf + 2*xx + 1]),
                                fmaxf(Cb[(2*yy+1)*hf + 2*xx],   Cb[(2*yy+1)*hf + 2*xx + 1]));
                if (MODE == 1) v += w1 * Tb[yy * h + xx] + w2 * m;
                else           v += w1 * m;
            }
            acc += wd[ky * 3 + kx] * v;
        }
    }
    out[idx] = acc;
}

// ---------------------------------------------------------------------------
// conv3x3 core (heads): Cin=88 in 8 chunks of 11, cp.async double-buffered.
// Tile 16x16, thread = 1x4 px x 4 co, smem rows padded to 20 floats.
// ---------------------------------------------------------------------------
#define CICH 11
#define SROW 20
#define SCH  (CICH * 18 * SROW)   // 3960 floats per buffer

struct LevelTile { int l, h, ty0, tx0; };

__device__ __forceinline__ LevelTile decode_tile(int bx) {
    LevelTile lt;
    int t;
    if (bx < 16)      { lt.l = 0; t = bx; }
    else if (bx < 20) { lt.l = 1; t = bx - 16; }
    else              { lt.l = bx - 18; t = 0; }
    lt.h = 64 >> lt.l;
    int tilesRow = (lt.l == 0) ? 4 : (lt.l == 1) ? 2 : 1;
    lt.ty0 = (t / tilesRow) * 16;
    lt.tx0 = (t % tilesRow) * 16;
    return lt;
}

__device__ __forceinline__ void stage_chunk(const float* __restrict__ inb, int cc,
                                            int h, int ty0, int tx0,
                                            float* sb, int tid) {
#pragma unroll 2
    for (int i = tid; i < CICH * 324; i += 256) {
        int ci = i / 324, r = i - ci * 324;
        int py = r / 18, px = r - py * 18;
        int gy = ty0 + py - 1, gx = tx0 + px - 1;
        bool ok = ((unsigned)gy < (unsigned)h) && ((unsigned)gx < (unsigned)h);
        const float* g = inb + ((size_t)(cc + ci) * h + (ok ? gy : 0)) * h + (ok ? gx : 0);
        cp_async4(smem_u32(sb + ci * (18 * SROW) + py * SROW + px), g, ok);
    }
}

__device__ __forceinline__ void conv3x3_core(
        const float* __restrict__ inb, const float4* __restrict__ wt4,
        int rs4, int c4, bool active,
        int h, int ty0, int tx0,
        float* s_in, int tid, int qy, int qx,
        float acc[4][4]) {
    const float* sp0 = s_in + qy * SROW + 4 * qx;
    stage_chunk(inb, 0, h, ty0, tx0, s_in, tid);
    cp_commit();

    const int NCH = WC / CICH;   // 8
    for (int k = 0; k < NCH; k++) {
        if (k + 1 < NCH) {
            stage_chunk(inb, (k + 1) * CICH, h, ty0, tx0, s_in + ((k + 1) & 1) * SCH, tid);
            cp_commit();
            cp_wait<1>();
        } else {
            cp_wait<0>();
        }
        __syncthreads();

        if (active) {
            const float* spk = sp0 + (k & 1) * SCH;
            for (int ci = 0; ci < CICH; ci++) {
                const float* s = spk + ci * (18 * SROW);
                float v[3][6];
#pragma unroll
                for (int r = 0; r < 3; r++) {
                    float4 u0 = *(const float4*)(s + r * SROW);
                    float2 u1 = *(const float2*)(s + r * SROW + 4);
                    v[r][0] = u0.x; v[r][1] = u0.y; v[r][2] = u0.z; v[r][3] = u0.w;
                    v[r][4] = u1.x; v[r][5] = u1.y;
                }
                int cig = k * CICH + ci;
                const float4* wp = wt4 + (size_t)cig * 9 * rs4 + c4;
#pragma unroll
                for (int ky = 0; ky < 3; ky++) {
#pragma unroll
                    for (int kx = 0; kx < 3; kx++) {
                        float4 w = wp[(ky * 3 + kx) * rs4];
#pragma unroll
                        for (int px2 = 0; px2 < 4; px2++) {
                            float vv = v[ky][px2 + kx];
                            acc[px2][0] += w.x * vv;
                            acc[px2][1] += w.y * vv;
                            acc[px2][2] += w.z * vv;
                            acc[px2][3] += w.w * vv;
                        }
                    }
                }
            }
        }
        __syncthreads();
    }
}

// ---------------------------------------------------------------------------
// Fused reg+cls tower conv layer: grid (23, 12, B). 64 regs, 4 blocks/SM.
// ---------------------------------------------------------------------------
__global__ void __launch_bounds__(256, 4) conv3x3_tower(
        const float* __restrict__ inR, const float* __restrict__ inC,
        const float* __restrict__ wtR, const float* __restrict__ wtC,
        const float* __restrict__ bR,  const float* __restrict__ bC,
        float* __restrict__ outR, float* __restrict__ outC) {
    __shared__ float s_in[2 * SCH];

    LevelTile lt = decode_tile(blockIdx.x);
    int b   = blockIdx.z;
    int tid = threadIdx.x;
    int lane = tid >> 6;
    int p    = tid & 63;
    int qx = p & 3, qy = p >> 2;

    int side  = blockIdx.y >= 6;
    int chunk = blockIdx.y - side * 6;
    const float* in  = side ? inC : inR;
    const float* wt  = side ? wtC : wtR;
    const float* bb  = side ? bC  : bR;
    float* out       = side ? outC : outR;

    int co0 = chunk * 16 + lane * 4;
    bool active = (co0 < WC);

    float acc[4][4];
    {
        float b0 = active ? bb[co0 + 0] : 0.f;
        float b1 = active ? bb[co0 + 1] : 0.f;
        float b2 = active ? bb[co0 + 2] : 0.f;
        float b3 = active ? bb[co0 + 3] : 0.f;
#pragma unroll
        for (int j = 0; j < 4; j++) { acc[j][0] = b0; acc[j][1] = b1; acc[j][2] = b2; acc[j][3] = b3; }
    }

    const float* inb = in + c_lvloff[lt.l] + (size_t)b * WC * lt.h * lt.h;
    conv3x3_core(inb, (const float4*)wt, WC >> 2, co0 >> 2, active,
                 lt.h, lt.ty0, lt.tx0, s_in, tid, qy, qx, acc);

    if (!active) return;
    int oy = lt.ty0 + qy, ox = lt.tx0 + 4 * qx;
    if (oy >= lt.h || ox >= lt.h) return;

    float* ob = out + c_lvloff[lt.l] + ((size_t)(b * WC + co0) * lt.h + oy) * lt.h + ox;
    size_t st = (size_t)lt.h * lt.h;
#pragma unroll
    for (int i = 0; i < 4; i++) {
        float4 r;
        r.x = fmaxf(acc[0][i], 0.f); r.y = fmaxf(acc[1][i], 0.f);
        r.z = fmaxf(acc[2][i], 0.f); r.w = fmaxf(acc[3][i], 0.f);
        *(float4*)(ob + i * st) = r;
    }
}

// ---------------------------------------------------------------------------
// Fused output convs: grid (23, 54, B).
//  y in [0,3): reg out (Cout 36, outCh 4, linear)
//  y in [3,54): cls out (Cout 810 / pad 812, outCh 90, sigmoid)
// ---------------------------------------------------------------------------
__global__ void __launch_bounds__(256, 4) conv3x3_out(
        const float* __restrict__ inR, const float* __restrict__ inC,
        const float* __restrict__ wtR, const float* __restrict__ wtC,
        const float* __restrict__ bR,  const float* __restrict__ bC,
        float* __restrict__ outR, float* __restrict__ outC) {
    __shared__ float s_in[2 * SCH];

    LevelTile lt = decode_tile(blockIdx.x);
    int b   = blockIdx.z;
    int tid = threadIdx.x;
    int lane = tid >> 6;
    int p    = tid & 63;
    int qx = p & 3, qy = p >> 2;

    bool isReg = (blockIdx.y < 3);
    int chunk  = isReg ? blockIdx.y : blockIdx.y - 3;
    int Cout   = isReg ? 36 : 810;
    int CoutP  = isReg ? 36 : 812;
    int outCh  = isReg ? 4 : 90;
    const float* in = isReg ? inR : inC;
    const float* wt = isReg ? wtR : wtC;
    const float* bb = isReg ? bR  : bC;
    float* out      = isReg ? outR : outC;

    int co0 = chunk * 16 + lane * 4;
    bool active = (co0 < Cout);

    float acc[4][4];
    {
        float b0 = (co0 + 0 < Cout) ? bb[co0 + 0] : 0.f;
        float b1 = (co0 + 1 < Cout) ? bb[co0 + 1] : 0.f;
        float b2 = (co0 + 2 < Cout) ? bb[co0 + 2] : 0.f;
        float b3 = (co0 + 3 < Cout) ? bb[co0 + 3] : 0.f;
#pragma unroll
        for (int j = 0; j < 4; j++) { acc[j][0] = b0; acc[j][1] = b1; acc[j][2] = b2; acc[j][3] = b3; }
    }

    const float* inb = in + c_lvloff[lt.l] + (size_t)b * WC * lt.h * lt.h;
    conv3x3_core(inb, (const float4*)wt, CoutP >> 2, co0 >> 2, active,
                 lt.h, lt.ty0, lt.tx0, s_in, tid, qy, qx, acc);

    if (!active) return;
    int oy = lt.ty0 + qy, ox = lt.tx0 + 4 * qx;
    if (oy >= lt.h || ox >= lt.h) return;

#pragma unroll
    for (int px2 = 0; px2 < 4; px2++) {
        int gai = c_aoff[lt.l] + (oy * lt.h + ox + px2) * 9;
#pragma unroll
        for (int i = 0; i < 4; i++) {
            int co = co0 + i;
            if (co >= Cout) break;
            int ai = co / outCh;
            int oc = co - ai * outCh;
            float vv = acc[px2][i];
            if (!isReg) vv = 1.f / (1.f + __expf(-vv));
            out[((size_t)b * ATOT + gai + ai) * outCh + oc] = vv;
        }
    }
}

// ---------------------------------------------------------------------------
// Anchors (RetinaNet-style, img_size=512, levels 3..7)
// ---------------------------------------------------------------------------
__global__ void anchors_kernel(float* __restrict__ out) {
    int i = blockIdx.x * blockDim.x + threadIdx.x;
    if (i >= ATOT) return;
    const int offs[6] = {0, 36864, 46080, 48384, 48960, 49104};
    int l = 0;
    while (i >= offs[l + 1]) l++;
    int fs = 64 >> l;
    float stride = (float)(8 << l);
    float size   = (float)(32 << l);
    int r = i - offs[l];
    int a = r % 9;
    int p = r / 9;
    int px = p % fs, py = p / fs;
    float cx = (px + 0.5f) * stride;
    float cy = (py + 0.5f) * stride;
    int ri = a / 3, si = a % 3;
    const float ratios[3] = {0.5f, 1.0f, 2.0f};
    float scale = exp2f((float)si * (1.0f / 3.0f));
    float sr = sqrtf(ratios[ri]);
    float w = size * scale / sr;
    float hh = size * scale * sr;
    out[i * 4 + 0] = cx - 0.5f * w;
    out[i * 4 + 1] = cy - 0.5f * hh;
    out[i * 4 + 2] = cx + 0.5f * w;
    out[i * 4 + 3] = cy + 0.5f * hh;
}

// ---------------------------------------------------------------------------
// Host orchestration
// ---------------------------------------------------------------------------
extern "C" void kernel_launch(void* const* d_in, const int* in_sizes, int n_in,
                              void* d_out, int out_size) {
    (void)in_sizes; (void)n_in; (void)out_size;
    using namespace cfg;

    const float* cIn[5]; const float* latw[5]; const float* latb[5];
    for (int l = 0; l < 5; l++) {
        cIn[l]  = (const float*)d_in[3 * l + 0];
        latw[l] = (const float*)d_in[3 * l + 1];
        latb[l] = (const float*)d_in[3 * l + 2];
    }
    const float* bif_dw  = (const float*)d_in[15];
    const float* bif_pw  = (const float*)d_in[16];
    const float* bif_pb  = (const float*)d_in[17];
    const float* bif_fw2 = (const float*)d_in[18];
    const float* bif_fw3 = (const float*)d_in[19];
    const float* reg_tw  = (const float*)d_in[20];
    const float* reg_tb  = (const float*)d_in[21];
    const float* reg_ow  = (const float*)d_in[22];
    const float* reg_ob  = (const float*)d_in[23];
    const float* cls_tw  = (const float*)d_in[24];
    const float* cls_tb  = (const float*)d_in[25];
    const float* cls_ow  = (const float*)d_in[26];
    const float* cls_ob  = (const float*)d_in[27];
    float* outp = (float*)d_out;

    float* S = nullptr;
    cudaGetSymbolAddress((void**)&S, g_scratch);
    float* P   = S + OFF_P;
    float* O   = S + OFF_O;
    float* T   = S + OFF_T;
    float* DW  = S + OFF_DW;
    float* HR1 = S + OFF_HR1;
    float* HR2 = S + OFF_HR2;
    float* HC1 = S + OFF_HC1;
    float* HC2 = S + OFF_HC2;
    float* WT  = S + OFF_WT;

    // ---- weight transposes ----
    for (int l = 0; l < 5; l++) {
        int tot = WC * CIN_LAT[l];
        transpose_w_kernel<<<(tot + 255) / 256, 256>>>(latw[l], WT + WT_LAT[l], WC, CIN_LAT[l], 1, WC);
    }
    transpose_w_kernel<<<dim3((WC*WC + 255) / 256, 1, 24), 256>>>(bif_pw, WT + WT_BIFPW, WC, WC, 1, WC);
    transpose_w_kernel<<<dim3((TWN + 255) / 256, 1, 4), 256>>>(reg_tw, WT + WT_REGTW, WC, WC, 9, WC);
    transpose_w_kernel<<<dim3((TWN + 255) / 256, 1, 4), 256>>>(cls_tw, WT + WT_CLSTW, WC, WC, 9, WC);
    transpose_w_kernel<<<(36*WC*9 + 255) / 256, 256>>>(reg_ow, WT + WT_REGOW, 36, WC, 9, 36);
    transpose_w_kernel<<<(810*WC*9 + 255) / 256, 256>>>(cls_ow, WT + WT_CLSOW, 810, WC, 9, 812);

    // ---- lateral 1x1 convs (no relu) ----
    for (int l = 0; l < 5; l++) {
        dim3 g((HW_[l] + 255) / 256, (WC + 15) / 16, BATCH);
        pw_kernel<false><<<g, 256>>>(cIn[l], WT + WT_LAT[l], latb[l], P + LVL_OFF[l],
                                     CIN_LAT[l], WC, HW_[l]);
    }

    // ---- BiFPN stages (split dw+pw everywhere, R13 structure) ----
    float* cur = P;
    float* nxt = O;
    for (int s = 0; s < 3; s++) {
        const float* dwW = bif_dw + (size_t)s * 8 * WC * 9;
        const float* pwT = WT + WT_BIFPW + (size_t)s * 8 * WC * WC;
        const float* pbb = bif_pb + (size_t)s * 8 * WC;
        const float* f2  = bif_fw2 + s * 10;
        const float* f3  = bif_fw3 + s * 9;

        auto pw = [&](int j, int h, float* dst) {
            dim3 g((h * h + 255) / 256, (WC + 15) / 16, BATCH);
            pw_kernel<true><<<g, 256>>>(DW, pwT + j * WC * WC, pbb + j * WC, dst, WC, WC, h * h);
        };
        auto sep_up = [&](int l, const float* A, const float* Bh, int j, const float* fwp, float* dst) {
            int h = HS[l], n = BATCH * WC * h * h;
            dw_fuse_kernel<0><<<(n + 255) / 256, 256>>>(A, Bh, nullptr, nullptr, dwW + j * WC * 9, fwp, DW, h);
            pw(j, h, dst);
        };
        auto sep3 = [&](int l, const float* A, const float* Tm, const float* Cf, int j, const float* fwp, float* dst) {
            int h = HS[l], n = BATCH * WC * h * h;
            dw_fuse_kernel<1><<<(n + 255) / 256, 256>>>(A, nullptr, Tm, Cf, dwW + j * WC * 9, fwp, DW, h);
            pw(j, h, dst);
        };
        auto sep_dn = [&](int l, const float* A, const float* Cf, int j, const float* fwp, float* dst) {
            int h = HS[l], n = BATCH * WC * h * h;
            dw_fuse_kernel<2><<<(n + 255) / 256, 256>>>(A, nullptr, nullptr, Cf, dwW + j * WC * 9, fwp, DW, h);
            pw(j, h, dst);
        };

        // top-down
        sep_up(3, cur + LVL_OFF[3], cur + LVL_OFF[4], 0, f2 + 0, T + TOFF[3]);   // p6t
        sep_up(2, cur + LVL_OFF[2], T + TOFF[3],      1, f2 + 2, T + TOFF[2]);   // p5t
        sep_up(1, cur + LVL_OFF[1], T + TOFF[2],      2, f2 + 4, T + TOFF[1]);   // p4t
        sep_up(0, cur + LVL_OFF[0], T + TOFF[1],      3, f2 + 6, nxt + LVL_OFF[0]); // p3o
        // bottom-up
        sep3(1, cur + LVL_OFF[1], T + TOFF[1], nxt + LVL_OFF[0], 4, f3 + 0, nxt + LVL_OFF[1]); // p4o
        sep3(2, cur + LVL_OFF[2], T + TOFF[2], nxt + LVL_OFF[1], 5, f3 + 3, nxt + LVL_OFF[2]); // p5o
        sep3(3, cur + LVL_OFF[3], T + TOFF[3], nxt + LVL_OFF[2], 6, f3 + 6, nxt + LVL_OFF[3]); // p6o
        sep_dn(4, cur + LVL_OFF[4], nxt + LVL_OFF[3], 7, f2 + 8, nxt + LVL_OFF[4]);            // p7o

        float* tmp = cur; cur = nxt; nxt = tmp;
    }
    // final pyramid is in `cur`

    // ---- heads: 4 fused tower layers + 1 fused output layer ----
    dim3 gT(23, 12, BATCH);
    dim3 gO(23, 54, BATCH);

    conv3x3_tower<<<gT, 256>>>(cur, cur,
                               WT + WT_REGTW + 0 * TWN, WT + WT_CLSTW + 0 * TWN,
                               reg_tb + 0,   cls_tb + 0,   HR1, HC1);
    conv3x3_tower<<<gT, 256>>>(HR1, HC1,
                               WT + WT_REGTW + 1 * TWN, WT + WT_CLSTW + 1 * TWN,
                               reg_tb + 88,  cls_tb + 88,  HR2, HC2);
    conv3x3_tower<<<gT, 256>>>(HR2, HC2,
                               WT + WT_REGTW + 2 * TWN, WT + WT_CLSTW + 2 * TWN,
                               reg_tb + 176, cls_tb + 176, HR1, HC1);
    conv3x3_tower<<<gT, 256>>>(HR1, HC1,
                               WT + WT_REGTW + 3 * TWN, WT + WT_CLSTW + 3 * TWN,
                               reg_tb + 264, cls_tb + 264, HR2, HC2);
    conv3x3_out<<<gO, 256>>>(HR2, HC2,
                             WT + WT_REGOW, WT + WT_CLSOW,
                             reg_ob, cls_ob,
                             outp + REG_BASE, outp);

    // ---- anchors ----
    anchors_kernel<<<(ATOT + 255) / 256, 256>>>(outp + ANCH_BASE);
}

// round 17
// speedup vs baseline: 1.2124x; 1.0859x over previous
#include <cuda_runtime.h>
#include <math.h>

// ---------------------------------------------------------------------------
// EfficientDet (BiFPN W=88, 3 stages, D=4 head) on GB300, fp32 direct convs.
// R17: R13 structure; head conv lane remap (co-quad = tid&3, pixel = tid>>2)
//      -> 4-way smem broadcast, crossbar 144 -> ~60 cyc per block-ci.
// ---------------------------------------------------------------------------

#define BATCH 4
#define WC 88
#define ATOT 49104

namespace cfg {
constexpr int HS[5]      = {64, 32, 16, 8, 4};
constexpr int HW_[5]     = {4096, 1024, 256, 64, 16};
constexpr int CIN_LAT[5] = {40, 80, 112, 192, 320};

constexpr long long REG_BASE  = (long long)BATCH * ATOT * 90;            // 17,677,440
constexpr long long ANCH_BASE = REG_BASE + (long long)BATCH * ATOT * 4;  // 18,463,104

constexpr int LVL_N[5]   = {BATCH*WC*4096, BATCH*WC*1024, BATCH*WC*256, BATCH*WC*64, BATCH*WC*16};
constexpr int LVL_OFF[5] = {0, 1441792, 1802240, 1892352, 1914880};
constexpr int PYR_N = 1920512;
constexpr int TOFF[5] = {0, 0, 360448, 450560, 0};   // td buffers (P4t,P5t,P6t)
constexpr int T_N = 473088;

constexpr int OFF_P   = 0;
constexpr int OFF_O   = OFF_P + PYR_N;
constexpr int OFF_T   = OFF_O + PYR_N;
constexpr int OFF_DW  = OFF_T + T_N;
constexpr int OFF_HR1 = OFF_DW + LVL_N[0];
constexpr int OFF_HR2 = OFF_HR1 + PYR_N;
constexpr int OFF_HC1 = OFF_HR2 + PYR_N;
constexpr int OFF_HC2 = OFF_HC1 + PYR_N;
constexpr int OFF_WT  = OFF_HC2 + PYR_N;

constexpr int WT_LAT[5] = {0, 3520, 10560, 20416, 37312};
constexpr int WT_BIFPW  = 65472;
constexpr int TWN       = WC * 9 * WC;                  // 69,696
constexpr int WT_REGTW  = WT_BIFPW + 24 * WC * WC;
constexpr int WT_CLSTW  = WT_REGTW + 4 * TWN;
constexpr int WT_REGOW  = WT_CLSTW + 4 * TWN;
constexpr int WT_CLSOW  = WT_REGOW + WC * 9 * 36;
constexpr int WT_TOTAL  = WT_CLSOW + WC * 9 * 812;
constexpr int SCRATCH_N = OFF_WT + WT_TOTAL;
}

// Zero-initialized scratch (padding lanes of transposed cls weights stay 0).
__device__ __align__(16) float g_scratch[cfg::SCRATCH_N];

// Level tables for the fused head-conv launches.
__constant__ int c_lvloff[5] = {0, 1441792, 1802240, 1892352, 1914880};
__constant__ int c_aoff[5]   = {0, 36864, 46080, 48384, 48960};

// ---------------------------------------------------------------------------
// cp.async helpers
// ---------------------------------------------------------------------------
__device__ __forceinline__ unsigned int smem_u32(const void* p) {
    return (unsigned int)__cvta_generic_to_shared(p);
}
__device__ __forceinline__ void cp_async4(unsigned int dst, const void* src, bool ok) {
    int sz = ok ? 4 : 0;
    asm volatile("cp.async.ca.shared.global [%0], [%1], 4, %2;"
                 :: "r"(dst), "l"(src), "r"(sz));
}
__device__ __forceinline__ void cp_commit() {
    asm volatile("cp.async.commit_group;");
}
template <int N>
__device__ __forceinline__ void cp_wait() {
    asm volatile("cp.async.wait_group %0;" :: "n"(N));
}

// ---------------------------------------------------------------------------
// Weight transpose: w[co][ci][k] -> wt[(ci*K+k)*CoutP + co]  (batched via z)
// ---------------------------------------------------------------------------
__global__ void transpose_w_kernel(const float* __restrict__ w, float* __restrict__ wt,
                                   int Cout, int Cin, int K, int CoutP) {
    int bidx = blockIdx.z;
    w  += (size_t)bidx * Cout * Cin * K;
    wt += (size_t)bidx * Cin * K * CoutP;
    int i = blockIdx.x * blockDim.x + threadIdx.x;
    int total = Cout * Cin * K;
    if (i >= total) return;
    int k  = i % K;
    int ci = (i / K) % Cin;
    int co = i / (K * Cin);
    wt[(ci * K + k) * CoutP + co] = w[i];
}

// ---------------------------------------------------------------------------
// Pointwise 1x1 conv (+bias, optional ReLU). Cout mult of 4 (=88).
// block 256 = 64 pixel-lanes x 4 co-lanes; each thread: 4 pixels x 4 co.
// (R13 version — strided pixels; R16's consecutive-px variant regressed.)
// ---------------------------------------------------------------------------
template <bool RELU>
__global__ void __launch_bounds__(256) pw_kernel(
        const float* __restrict__ in, const float* __restrict__ wt,
        const float* __restrict__ bias, float* __restrict__ out,
        int Cin, int Cout, int HW) {
    int tid  = threadIdx.x;
    int base = blockIdx.x * 256 + (tid & 63);
    int lane = tid >> 6;
    int co0  = blockIdx.y * 16 + lane * 4;
    int b    = blockIdx.z;
    if (co0 >= Cout || base >= HW) return;

    int pix[4];
#pragma unroll
    for (int j = 0; j < 4; j++) {
        int p = base + j * 64;
        pix[j] = (p < HW) ? p : (HW - 1);
    }

    float a[4][4];
#pragma unroll
    for (int j = 0; j < 4; j++) {
        a[j][0] = bias[co0 + 0]; a[j][1] = bias[co0 + 1];
        a[j][2] = bias[co0 + 2]; a[j][3] = bias[co0 + 3];
    }

    const float* inb = in + (size_t)b * Cin * HW;
    const float4* wt4 = (const float4*)wt;
    int cs4 = Cout >> 2;
    int w0i = co0 >> 2;
    for (int ci = 0; ci < Cin; ci++) {
        float4 w = wt4[ci * cs4 + w0i];
        const float* row = inb + (size_t)ci * HW;
#pragma unroll
        for (int j = 0; j < 4; j++) {
            float v = row[pix[j]];
            a[j][0] += w.x * v; a[j][1] += w.y * v; a[j][2] += w.z * v; a[j][3] += w.w * v;
        }
    }

    size_t ob0 = ((size_t)(b * Cout + co0)) * HW;
#pragma unroll
    for (int j = 0; j < 4; j++) {
        int p = base + j * 64;
        if (p >= HW) break;
        float v0 = a[j][0], v1 = a[j][1], v2 = a[j][2], v3 = a[j][3];
        if (RELU) { v0 = fmaxf(v0, 0.f); v1 = fmaxf(v1, 0.f); v2 = fmaxf(v2, 0.f); v3 = fmaxf(v3, 0.f); }
        out[ob0 + p]                  = v0;
        out[ob0 + (size_t)HW + p]     = v1;
        out[ob0 + 2 * (size_t)HW + p] = v2;
        out[ob0 + 3 * (size_t)HW + p] = v3;
    }
}

// ---------------------------------------------------------------------------
// Depthwise 3x3 with fused normalized-fusion input, computed on the fly.
// MODE 0: fuse2 + up2(Bh)    MODE 1: fuse3 + down2(Cf)    MODE 2: fuse2 + down2(Cf)
// ---------------------------------------------------------------------------
template <int MODE>
__global__ void dw_fuse_kernel(const float* __restrict__ A, const float* __restrict__ Bh,
                               const float* __restrict__ Tm, const float* __restrict__ Cf,
                               const float* __restrict__ dww, const float* __restrict__ fw,
                               float* __restrict__ out, int h) {
    int idx = blockIdx.x * blockDim.x + threadIdx.x;
    int total = BATCH * WC * h * h;
    if (idx >= total) return;
    int x = idx % h;
    int y = (idx / h) % h;
    int c = (idx / (h * h)) % WC;
    int b = idx / (WC * h * h);

    float w0, w1, w2 = 0.f;
    if (MODE == 1) {
        w0 = fmaxf(fw[0], 0.f); w1 = fmaxf(fw[1], 0.f); w2 = fmaxf(fw[2], 0.f);
        float s = w0 + w1 + w2 + 1e-4f; w0 /= s; w1 /= s; w2 /= s;
    } else {
        w0 = fmaxf(fw[0], 0.f); w1 = fmaxf(fw[1], 0.f);
        float s = w0 + w1 + 1e-4f; w0 /= s; w1 /= s;
    }

    int h2 = h >> 1, hf = h << 1;
    size_t chan = (size_t)(b * WC + c);
    const float* Ab = A + chan * h * h;
    const float* Bb = (MODE == 0) ? Bh + chan * h2 * h2 : nullptr;
    const float* Tb = (MODE == 1) ? Tm + chan * h * h : nullptr;
    const float* Cb = (MODE != 0) ? Cf + chan * hf * hf : nullptr;
    const float* wd = dww + c * 9;

    float acc = 0.f;
#pragma unroll
    for (int ky = 0; ky < 3; ky++) {
        int yy = y + ky - 1;
        if ((unsigned)yy >= (unsigned)h) continue;
#pragma unroll
        for (int kx = 0; kx < 3; kx++) {
            int xx = x + kx - 1;
            if ((unsigned)xx >= (unsigned)h) continue;
            float v = w0 * Ab[yy * h + xx];
            if (MODE == 0) {
                v += w1 * Bb[(yy >> 1) * h2 + (xx >> 1)];
            } else {
                float m = fmaxf(fmaxf(Cb[(2*yy)*hf + 2*xx],     Cb[(2*yy)*hf + 2*xx + 1]),
                                fmaxf(Cb[(2*yy+1)*hf + 2*xx],   Cb[(2*yy+1)*hf + 2*xx + 1]));
                if (MODE == 1) v += w1 * Tb[yy * h + xx] + w2 * m;
                else           v += w1 * m;
            }
            acc += wd[ky * 3 + kx] * v;
        }
    }
    out[idx] = acc;
}

// ---------------------------------------------------------------------------
// conv3x3 core (heads): Cin=88 in 8 chunks of 11, cp.async double-buffered.
// Tile 16x16; thread = 1x4 px x 4 co. Lane map: quad = tid&3 (co), pxg = tid>>2.
// Within a warp: 8 pixel-groups x 4 co-quads -> input LDS has 8 distinct
// addresses + 4-way broadcast (1-2 crossbar phases instead of 4).
// ---------------------------------------------------------------------------
#define CICH 11
#define SROW 20
#define SCH  (CICH * 18 * SROW)   // 3960 floats per buffer

struct LevelTile { int l, h, ty0, tx0; };

__device__ __forceinline__ LevelTile decode_tile(int bx) {
    LevelTile lt;
    int t;
    if (bx < 16)      { lt.l = 0; t = bx; }
    else if (bx < 20) { lt.l = 1; t = bx - 16; }
    else              { lt.l = bx - 18; t = 0; }
    lt.h = 64 >> lt.l;
    int tilesRow = (lt.l == 0) ? 4 : (lt.l == 1) ? 2 : 1;
    lt.ty0 = (t / tilesRow) * 16;
    lt.tx0 = (t % tilesRow) * 16;
    return lt;
}

__device__ __forceinline__ void stage_chunk(const float* __restrict__ inb, int cc,
                                            int h, int ty0, int tx0,
                                            float* sb, int tid) {
#pragma unroll 2
    for (int i = tid; i < CICH * 324; i += 256) {
        int ci = i / 324, r = i - ci * 324;
        int py = r / 18, px = r - py * 18;
        int gy = ty0 + py - 1, gx = tx0 + px - 1;
        bool ok = ((unsigned)gy < (unsigned)h) && ((unsigned)gx < (unsigned)h);
        const float* g = inb + ((size_t)(cc + ci) * h + (ok ? gy : 0)) * h + (ok ? gx : 0);
        cp_async4(smem_u32(sb + ci * (18 * SROW) + py * SROW + px), g, ok);
    }
}

__device__ __forceinline__ void conv3x3_core(
        const float* __restrict__ inb, const float4* __restrict__ wt4,
        int rs4, int c4, bool active,
        int h, int ty0, int tx0,
        float* s_in, int tid, int qy, int qx,
        float acc[4][4]) {
    const float* sp0 = s_in + qy * SROW + 4 * qx;
    stage_chunk(inb, 0, h, ty0, tx0, s_in, tid);
    cp_commit();

    const int NCH = WC / CICH;   // 8
    for (int k = 0; k < NCH; k++) {
        if (k + 1 < NCH) {
            stage_chunk(inb, (k + 1) * CICH, h, ty0, tx0, s_in + ((k + 1) & 1) * SCH, tid);
            cp_commit();
            cp_wait<1>();
        } else {
            cp_wait<0>();
        }
        __syncthreads();

        if (active) {
            const float* spk = sp0 + (k & 1) * SCH;
            for (int ci = 0; ci < CICH; ci++) {
                const float* s = spk + ci * (18 * SROW);
                float v[3][6];
#pragma unroll
                for (int r = 0; r < 3; r++) {
                    float4 u0 = *(const float4*)(s + r * SROW);
                    float2 u1 = *(const float2*)(s + r * SROW + 4);
                    v[r][0] = u0.x; v[r][1] = u0.y; v[r][2] = u0.z; v[r][3] = u0.w;
                    v[r][4] = u1.x; v[r][5] = u1.y;
                }
                int cig = k * CICH + ci;
                const float4* wp = wt4 + (size_t)cig * 9 * rs4 + c4;
#pragma unroll
                for (int ky = 0; ky < 3; ky++) {
#pragma unroll
                    for (int kx = 0; kx < 3; kx++) {
                        float4 w = wp[(ky * 3 + kx) * rs4];
#pragma unroll
                        for (int px2 = 0; px2 < 4; px2++) {
                            float vv = v[ky][px2 + kx];
                            acc[px2][0] += w.x * vv;
                            acc[px2][1] += w.y * vv;
                            acc[px2][2] += w.z * vv;
                            acc[px2][3] += w.w * vv;
                        }
                    }
                }
            }
        }
        __syncthreads();
    }
}

// ---------------------------------------------------------------------------
// Fused reg+cls tower conv layer: grid (23, 12, B). 64 regs, 4 blocks/SM.
// Lane map: quad = tid&3 (co-quad), pixel-group = tid>>2.
// ---------------------------------------------------------------------------
__global__ void __launch_bounds__(256, 4) conv3x3_tower(
        const float* __restrict__ inR, const float* __restrict__ inC,
        const float* __restrict__ wtR, const float* __restrict__ wtC,
        const float* __restrict__ bR,  const float* __restrict__ bC,
        float* __restrict__ outR, float* __restrict__ outC) {
    __shared__ float s_in[2 * SCH];

    LevelTile lt = decode_tile(blockIdx.x);
    int b   = blockIdx.z;
    int tid = threadIdx.x;
    int quad = tid & 3;          // co-quad within 16-co chunk
    int p    = tid >> 2;         // pixel-group 0..63
    int qx = p & 3, qy = p >> 2;

    int side  = blockIdx.y >= 6;
    int chunk = blockIdx.y - side * 6;
    const float* in  = side ? inC : inR;
    const float* wt  = side ? wtC : wtR;
    const float* bb  = side ? bC  : bR;
    float* out       = side ? outC : outR;

    int co0 = chunk * 16 + quad * 4;
    bool active = (co0 < WC);

    float acc[4][4];
    {
        float b0 = active ? bb[co0 + 0] : 0.f;
        float b1 = active ? bb[co0 + 1] : 0.f;
        float b2 = active ? bb[co0 + 2] : 0.f;
        float b3 = active ? bb[co0 + 3] : 0.f;
#pragma unroll
        for (int j = 0; j < 4; j++) { acc[j][0] = b0; acc[j][1] = b1; acc[j][2] = b2; acc[j][3] = b3; }
    }

    const float* inb = in + c_lvloff[lt.l] + (size_t)b * WC * lt.h * lt.h;
    conv3x3_core(inb, (const float4*)wt, WC >> 2, co0 >> 2, active,
                 lt.h, lt.ty0, lt.tx0, s_in, tid, qy, qx, acc);

    if (!active) return;
    int oy = lt.ty0 + qy, ox = lt.tx0 + 4 * qx;
    if (oy >= lt.h || ox >= lt.h) return;

    float* ob = out + c_lvloff[lt.l] + ((size_t)(b * WC + co0) * lt.h + oy) * lt.h + ox;
    size_t st = (size_t)lt.h * lt.h;
#pragma unroll
    for (int i = 0; i < 4; i++) {
        float4 r;
        r.x = fmaxf(acc[0][i], 0.f); r.y = fmaxf(acc[1][i], 0.f);
        r.z = fmaxf(acc[2][i], 0.f); r.w = fmaxf(acc[3][i], 0.f);
        *(float4*)(ob + i * st) = r;
    }
}

// ---------------------------------------------------------------------------
// Fused output convs: grid (23, 54, B).
//  y in [0,3): reg out (Cout 36, outCh 4, linear)
//  y in [3,54): cls out (Cout 810 / pad 812, outCh 90, sigmoid)
// ---------------------------------------------------------------------------
__global__ void __launch_bounds__(256, 4) conv3x3_out(
        const float* __restrict__ inR, const float* __restrict__ inC,
        const float* __restrict__ wtR, const float* __restrict__ wtC,
        const float* __restrict__ bR,  const float* __restrict__ bC,
        float* __restrict__ outR, float* __restrict__ outC) {
    __shared__ float s_in[2 * SCH];

    LevelTile lt = decode_tile(blockIdx.x);
    int b   = blockIdx.z;
    int tid = threadIdx.x;
    int quad = tid & 3;
    int p    = tid >> 2;
    int qx = p & 3, qy = p >> 2;

    bool isReg = (blockIdx.y < 3);
    int chunk  = isReg ? blockIdx.y : blockIdx.y - 3;
    int Cout   = isReg ? 36 : 810;
    int CoutP  = isReg ? 36 : 812;
    int outCh  = isReg ? 4 : 90;
    const float* in = isReg ? inR : inC;
    const float* wt = isReg ? wtR : wtC;
    const float* bb = isReg ? bR  : bC;
    float* out      = isReg ? outR : outC;

    int co0 = chunk * 16 + quad * 4;
    bool active = (co0 < Cout);

    float acc[4][4];
    {
        float b0 = (co0 + 0 < Cout) ? bb[co0 + 0] : 0.f;
        float b1 = (co0 + 1 < Cout) ? bb[co0 + 1] : 0.f;
        float b2 = (co0 + 2 < Cout) ? bb[co0 + 2] : 0.f;
        float b3 = (co0 + 3 < Cout) ? bb[co0 + 3] : 0.f;
#pragma unroll
        for (int j = 0; j < 4; j++) { acc[j][0] = b0; acc[j][1] = b1; acc[j][2] = b2; acc[j][3] = b3; }
    }

    const float* inb = in + c_lvloff[lt.l] + (size_t)b * WC * lt.h * lt.h;
    conv3x3_core(inb, (const float4*)wt, CoutP >> 2, co0 >> 2, active,
                 lt.h, lt.ty0, lt.tx0, s_in, tid, qy, qx, acc);

    if (!active) return;
    int oy = lt.ty0 + qy, ox = lt.tx0 + 4 * qx;
    if (oy >= lt.h || ox >= lt.h) return;

#pragma unroll
    for (int px2 = 0; px2 < 4; px2++) {
        int gai = c_aoff[lt.l] + (oy * lt.h + ox + px2) * 9;
#pragma unroll
        for (int i = 0; i < 4; i++) {
            int co = co0 + i;
            if (co >= Cout) break;
            int ai = co / outCh;
            int oc = co - ai * outCh;
            float vv = acc[px2][i];
            if (!isReg) vv = 1.f / (1.f + __expf(-vv));
            out[((size_t)b * ATOT + gai + ai) * outCh + oc] = vv;
        }
    }
}

// ---------------------------------------------------------------------------
// Anchors (RetinaNet-style, img_size=512, levels 3..7)
// ---------------------------------------------------------------------------
__global__ void anchors_kernel(float* __restrict__ out) {
    int i = blockIdx.x * blockDim.x + threadIdx.x;
    if (i >= ATOT) return;
    const int offs[6] = {0, 36864, 46080, 48384, 48960, 49104};
    int l = 0;
    while (i >= offs[l + 1]) l++;
    int fs = 64 >> l;
    float stride = (float)(8 << l);
    float size   = (float)(32 << l);
    int r = i - offs[l];
    int a = r % 9;
    int p = r / 9;
    int px = p % fs, py = p / fs;
    float cx = (px + 0.5f) * stride;
    float cy = (py + 0.5f) * stride;
    int ri = a / 3, si = a % 3;
    const float ratios[3] = {0.5f, 1.0f, 2.0f};
    float scale = exp2f((float)si * (1.0f / 3.0f));
    float sr = sqrtf(ratios[ri]);
    float w = size * scale / sr;
    float hh = size * scale * sr;
    out[i * 4 + 0] = cx - 0.5f * w;
    out[i * 4 + 1] = cy - 0.5f * hh;
    out[i * 4 + 2] = cx + 0.5f * w;
    out[i * 4 + 3] = cy + 0.5f * hh;
}

// ---------------------------------------------------------------------------
// Host orchestration
// ---------------------------------------------------------------------------
extern "C" void kernel_launch(void* const* d_in, const int* in_sizes, int n_in,
                              void* d_out, int out_size) {
    (void)in_sizes; (void)n_in; (void)out_size;
    using namespace cfg;

    const float* cIn[5]; const float* latw[5]; const float* latb[5];
    for (int l = 0; l < 5; l++) {
        cIn[l]  = (const float*)d_in[3 * l + 0];
        latw[l] = (const float*)d_in[3 * l + 1];
        latb[l] = (const float*)d_in[3 * l + 2];
    }
    const float* bif_dw  = (const float*)d_in[15];
    const float* bif_pw  = (const float*)d_in[16];
    const float* bif_pb  = (const float*)d_in[17];
    const float* bif_fw2 = (const float*)d_in[18];
    const float* bif_fw3 = (const float*)d_in[19];
    const float* reg_tw  = (const float*)d_in[20];
    const float* reg_tb  = (const float*)d_in[21];
    const float* reg_ow  = (const float*)d_in[22];
    const float* reg_ob  = (const float*)d_in[23];
    const float* cls_tw  = (const float*)d_in[24];
    const float* cls_tb  = (const float*)d_in[25];
    const float* cls_ow  = (const float*)d_in[26];
    const float* cls_ob  = (const float*)d_in[27];
    float* outp = (float*)d_out;

    float* S = nullptr;
    cudaGetSymbolAddress((void**)&S, g_scratch);
    float* P   = S + OFF_P;
    float* O   = S + OFF_O;
    float* T   = S + OFF_T;
    float* DW  = S + OFF_DW;
    float* HR1 = S + OFF_HR1;
    float* HR2 = S + OFF_HR2;
    float* HC1 = S + OFF_HC1;
    float* HC2 = S + OFF_HC2;
    float* WT  = S + OFF_WT;

    // ---- weight transposes ----
    for (int l = 0; l < 5; l++) {
        int tot = WC * CIN_LAT[l];
        transpose_w_kernel<<<(tot + 255) / 256, 256>>>(latw[l], WT + WT_LAT[l], WC, CIN_LAT[l], 1, WC);
    }
    transpose_w_kernel<<<dim3((WC*WC + 255) / 256, 1, 24), 256>>>(bif_pw, WT + WT_BIFPW, WC, WC, 1, WC);
    transpose_w_kernel<<<dim3((TWN + 255) / 256, 1, 4), 256>>>(reg_tw, WT + WT_REGTW, WC, WC, 9, WC);
    transpose_w_kernel<<<dim3((TWN + 255) / 256, 1, 4), 256>>>(cls_tw, WT + WT_CLSTW, WC, WC, 9, WC);
    transpose_w_kernel<<<(36*WC*9 + 255) / 256, 256>>>(reg_ow, WT + WT_REGOW, 36, WC, 9, 36);
    transpose_w_kernel<<<(810*WC*9 + 255) / 256, 256>>>(cls_ow, WT + WT_CLSOW, 810, WC, 9, 812);

    // ---- lateral 1x1 convs (no relu) ----
    for (int l = 0; l < 5; l++) {
        dim3 g((HW_[l] + 255) / 256, (WC + 15) / 16, BATCH);
        pw_kernel<false><<<g, 256>>>(cIn[l], WT + WT_LAT[l], latb[l], P + LVL_OFF[l],
                                     CIN_LAT[l], WC, HW_[l]);
    }

    // ---- BiFPN stages (split dw+pw everywhere, R13 structure) ----
    float* cur = P;
    float* nxt = O;
    for (int s = 0; s < 3; s++) {
        const float* dwW = bif_dw + (size_t)s * 8 * WC * 9;
        const float* pwT = WT + WT_BIFPW + (size_t)s * 8 * WC * WC;
        const float* pbb = bif_pb + (size_t)s * 8 * WC;
        const float* f2  = bif_fw2 + s * 10;
        const float* f3  = bif_fw3 + s * 9;

        auto pw = [&](int j, int h, float* dst) {
            dim3 g((h * h + 255) / 256, (WC + 15) / 16, BATCH);
            pw_kernel<true><<<g, 256>>>(DW, pwT + j * WC * WC, pbb + j * WC, dst, WC, WC, h * h);
        };
        auto sep_up = [&](int l, const float* A, const float* Bh, int j, const float* fwp, float* dst) {
            int h = HS[l], n = BATCH * WC * h * h;
            dw_fuse_kernel<0><<<(n + 255) / 256, 256>>>(A, Bh, nullptr, nullptr, dwW + j * WC * 9, fwp, DW, h);
            pw(j, h, dst);
        };
        auto sep3 = [&](int l, const float* A, const float* Tm, const float* Cf, int j, const float* fwp, float* dst) {
            int h = HS[l], n = BATCH * WC * h * h;
            dw_fuse_kernel<1><<<(n + 255) / 256, 256>>>(A, nullptr, Tm, Cf, dwW + j * WC * 9, fwp, DW, h);
            pw(j, h, dst);
        };
        auto sep_dn = [&](int l, const float* A, const float* Cf, int j, const float* fwp, float* dst) {
            int h = HS[l], n = BATCH * WC * h * h;
            dw_fuse_kernel<2><<<(n + 255) / 256, 256>>>(A, nullptr, nullptr, Cf, dwW + j * WC * 9, fwp, DW, h);
            pw(j, h, dst);
        };

        // top-down
        sep_up(3, cur + LVL_OFF[3], cur + LVL_OFF[4], 0, f2 + 0, T + TOFF[3]);   // p6t
        sep_up(2, cur + LVL_OFF[2], T + TOFF[3],      1, f2 + 2, T + TOFF[2]);   // p5t
        sep_up(1, cur + LVL_OFF[1], T + TOFF[2],      2, f2 + 4, T + TOFF[1]);   // p4t
        sep_up(0, cur + LVL_OFF[0], T + TOFF[1],      3, f2 + 6, nxt + LVL_OFF[0]); // p3o
        // bottom-up
        sep3(1, cur + LVL_OFF[1], T + TOFF[1], nxt + LVL_OFF[0], 4, f3 + 0, nxt + LVL_OFF[1]); // p4o
        sep3(2, cur + LVL_OFF[2], T + TOFF[2], nxt + LVL_OFF[1], 5, f3 + 3, nxt + LVL_OFF[2]); // p5o
        sep3(3, cur + LVL_OFF[3], T + TOFF[3], nxt + LVL_OFF[2], 6, f3 + 6, nxt + LVL_OFF[3]); // p6o
        sep_dn(4, cur + LVL_OFF[4], nxt + LVL_OFF[3], 7, f2 + 8, nxt + LVL_OFF[4]);            // p7o

        float* tmp = cur; cur = nxt; nxt = tmp;
    }
    // final pyramid is in `cur`

    // ---- heads: 4 fused tower layers + 1 fused output layer ----
    dim3 gT(23, 12, BATCH);
    dim3 gO(23, 54, BATCH);

    conv3x3_tower<<<gT, 256>>>(cur, cur,
                               WT + WT_REGTW + 0 * TWN, WT + WT_CLSTW + 0 * TWN,
                               reg_tb + 0,   cls_tb + 0,   HR1, HC1);
    conv3x3_tower<<<gT, 256>>>(HR1, HC1,
                               WT + WT_REGTW + 1 * TWN, WT + WT_CLSTW + 1 * TWN,
                               reg_tb + 88,  cls_tb + 88,  HR2, HC2);
    conv3x3_tower<<<gT, 256>>>(HR2, HC2,
                               WT + WT_REGTW + 2 * TWN, WT + WT_CLSTW + 2 * TWN,
                               reg_tb + 176, cls_tb + 176, HR1, HC1);
    conv3x3_tower<<<gT, 256>>>(HR1, HC1,
                               WT + WT_REGTW + 3 * TWN, WT + WT_CLSTW + 3 * TWN,
                               reg_tb + 264, cls_tb + 264, HR2, HC2);
    conv3x3_out<<<gO, 256>>>(HR2, HC2,
                             WT + WT_REGOW, WT + WT_CLSOW,
                             reg_ob, cls_ob,
                             outp + REG_BASE, outp);

    // ---- anchors ----
    anchors_kernel<<<(ATOT + 255) / 256, 256>>>(outp + ANCH_BASE);
}